// round 9
// baseline (speedup 1.0000x reference)
#include <cuda_runtime.h>

#define NPIX 1024
#define NVCH 64
#define RB 128          // output rows per conv block

__device__ float g_cube[(size_t)NVCH * NPIX * NPIX];   // 256 MB scratch
__device__ float g_g1d[8];

// ---------------------------------------------------------------- zero cube
__global__ __launch_bounds__(256) void zero_k() {
    float4* p = reinterpret_cast<float4*>(g_cube);
    const int n4 = NVCH * NPIX * NPIX / 4;
    float4 z = make_float4(0.f, 0.f, 0.f, 0.f);
    for (int i = blockIdx.x * 256 + threadIdx.x; i < n4; i += gridDim.x * 256)
        p[i] = z;
}

// ------------------------------------------------- recover separable 1D taps
__global__ void prep_k(const float* __restrict__ k2d) {
    int k = threadIdx.x;
    if (k < 7) {
        float s = 0.f;
        #pragma unroll
        for (int j = 0; j < 7; j++) s += k2d[k * 7 + j];
        g_g1d[k] = s;
    }
}

// ---------------------------------------------------------------- scatter
__global__ __launch_bounds__(256) void scatter_k(
    const float* __restrict__ pos,
    const float* __restrict__ vel,
    const float* __restrict__ flx,
    const float* __restrict__ vax,
    int M)
{
    int i = blockIdx.x * 256 + threadIdx.x;
    if (i >= M) return;

    float2 p = reinterpret_cast<const float2*>(pos)[i];
    float v  = vel[i];
    float f  = flx[i];

    float vel0 = __ldg(&vax[0]);
    float dv   = __fsub_rn(__ldg(&vax[1]), vel0);

    const float FOVH = 51.15f;
    int ix = (int)floorf(__fmul_rn(__fadd_rn(p.x, FOVH), 10.0f));
    int iy = (int)floorf(__fmul_rn(__fadd_rn(p.y, FOVH), 10.0f));
    int iv = (int)floorf(__fdiv_rn(__fsub_rn(v, vel0), dv));

    if ((unsigned)(ix + 4) >= (unsigned)(NPIX + 8)) return;
    if ((unsigned)(iy + 4) >= (unsigned)(NPIX + 8)) return;
    if ((unsigned)iv >= (unsigned)NVCH) return;

    int flat = (iv * NPIX + iy) * NPIX + ix;
    if ((unsigned)flat < (unsigned)(NVCH * NPIX * NPIX))
        atomicAdd(&g_cube[flat], f);
}

// -------- register-streaming separable 7x7 conv, no shuffles, with an
// EXPLICIT depth-2 load pipeline: triple-buffered row loads (ba/bl/br[3]);
// step `it` issues the 3 LDG.128s for row it+2 and computes row `it` from
// the buffer filled two steps earlier -> ~2x in-flight loads per warp at
// the same occupancy. Chunk unroll = 21 = lcm(7-ring, 3-buffer).

#define Z4 make_float4(0.f, 0.f, 0.f, 0.f)

#define VERT(JJ, comp)                                                        \
    (g0*h[((JJ)+1)%7].comp + g1*h[((JJ)+2)%7].comp + g2*h[((JJ)+3)%7].comp +  \
     g3*h[((JJ)+4)%7].comp + g4*h[((JJ)+5)%7].comp + g5*h[((JJ)+6)%7].comp +  \
     g6*h[(JJ)%7].comp)

#define CSTEP(J)                                                              \
{                                                                             \
    const int it = base + (J);                                                \
    const int yh = y0 - 3 + it;                                               \
    /* issue loads for row it+2 into buffer slot (J+2)%3 */                   \
    {                                                                         \
        const int yn = yh + 2;                                                \
        float4 na = Z4, nl = Z4, nr = Z4;                                     \
        if ((it + 2 < RB + 6) && (unsigned)yn < (unsigned)NPIX) {             \
            const float* rp = cube + (size_t)yn * NPIX;                       \
            na = *(const float4*)(rp + c);                                    \
            if (c >= 4)        nl = *(const float4*)(rp + c - 4);             \
            if (c + 7 < NPIX)  nr = *(const float4*)(rp + c + 4);             \
        }                                                                     \
        ba[((J)+2)%3] = na; bl[((J)+2)%3] = nl; br[((J)+2)%3] = nr;           \
    }                                                                         \
    float4 a  = ba[(J)%3];                                                    \
    float4 hl = bl[(J)%3];                                                    \
    float4 hr = br[(J)%3];                                                    \
    float4 hx;                                                                \
    hx.x = hl.y*g0 + hl.z*g1 + hl.w*g2 + a.x*g3 + a.y*g4 + a.z*g5 + a.w*g6;   \
    hx.y = hl.z*g0 + hl.w*g1 + a.x*g2 + a.y*g3 + a.z*g4 + a.w*g5 + hr.x*g6;   \
    hx.z = hl.w*g0 + a.x*g1 + a.y*g2 + a.z*g3 + a.w*g4 + hr.x*g5 + hr.y*g6;   \
    hx.w = a.x*g0 + a.y*g1 + a.z*g2 + a.w*g3 + hr.x*g4 + hr.y*g5 + hr.z*g6;   \
    h[(J)%7] = hx;                                                            \
    if (it >= 6) {                                                            \
        float4 o;                                                             \
        o.x = VERT(J, x); o.y = VERT(J, y);                                   \
        o.z = VERT(J, z); o.w = VERT(J, w);                                   \
        *(float4*)(outc + (size_t)(yh - 3) * NPIX + c) = o;                   \
    }                                                                         \
}

#define WARMLOAD(SLOT, IT)                                                    \
{                                                                             \
    const int yn = y0 - 3 + (IT);                                             \
    float4 na = Z4, nl = Z4, nr = Z4;                                         \
    if ((unsigned)yn < (unsigned)NPIX) {                                      \
        const float* rp = cube + (size_t)yn * NPIX;                           \
        na = *(const float4*)(rp + c);                                        \
        if (c >= 4)        nl = *(const float4*)(rp + c - 4);                 \
        if (c + 7 < NPIX)  nr = *(const float4*)(rp + c + 4);                 \
    }                                                                         \
    ba[SLOT] = na; bl[SLOT] = nl; br[SLOT] = nr;                              \
}

__global__ __launch_bounds__(256, 3) void conv_k(float* __restrict__ out) {
    const int lane = threadIdx.x & 31;
    const int wrp  = threadIdx.x >> 5;
    const int ch   = blockIdx.y;
    const int y0   = blockIdx.x * RB;
    const int c    = (wrp << 7) + (lane << 2);      // global column base (x4)

    const float* __restrict__ cube = g_cube + (size_t)ch * (NPIX * NPIX);
    float* __restrict__ outc = out + (size_t)ch * (NPIX * NPIX);

    const float g0 = g_g1d[0], g1 = g_g1d[1], g2 = g_g1d[2], g3 = g_g1d[3],
                g4 = g_g1d[4], g5 = g_g1d[5], g6 = g_g1d[6];

    float4 h[7];
    float4 ba[3], bl[3], br[3];

    // warmup: rows 0 and 1 into buffer slots 0 and 1
    WARMLOAD(0, 0)
    WARMLOAD(1, 1)

    // 134 producer rows: 6 chunks of 21 (it 0..125) + 8-step tail (126..133).
    // 126 % 3 == 0 and 126 % 7 == 0, so the tail reuses the same macro.
    #pragma unroll 1
    for (int base = 0; base < 126; base += 21) {
        CSTEP(0)  CSTEP(1)  CSTEP(2)  CSTEP(3)  CSTEP(4)  CSTEP(5)  CSTEP(6)
        CSTEP(7)  CSTEP(8)  CSTEP(9)  CSTEP(10) CSTEP(11) CSTEP(12) CSTEP(13)
        CSTEP(14) CSTEP(15) CSTEP(16) CSTEP(17) CSTEP(18) CSTEP(19) CSTEP(20)
    }
    {
        const int base = 126;
        CSTEP(0) CSTEP(1) CSTEP(2) CSTEP(3) CSTEP(4) CSTEP(5) CSTEP(6) CSTEP(7)
    }
}

extern "C" void kernel_launch(void* const* d_in, const int* in_sizes, int n_in,
                              void* d_out, int out_size) {
    const float* pos = (const float*)d_in[0];   // pos_img (M,2)
    const float* vel = (const float*)d_in[1];   // vel_chan (M,)
    const float* flx = (const float*)d_in[2];   // flux (M,)
    const float* vax = (const float*)d_in[3];   // vel_axis (64,)
    const float* k2d = (const float*)d_in[4];   // kernel2d (49,)
    float* out = (float*)d_out;

    int M = in_sizes[1];

    zero_k<<<4736, 256>>>();
    prep_k<<<1, 32>>>(k2d);
    scatter_k<<<(M + 255) / 256, 256>>>(pos, vel, flx, vax, M);

    dim3 grid(NPIX / RB, NVCH);
    conv_k<<<grid, 256>>>(out);
}

// round 10
// speedup vs baseline: 1.3725x; 1.3725x over previous
#include <cuda_runtime.h>
#include <cstdint>

#define NPIX 1024
#define NVCH 64
#define RB 128          // output rows per conv block
#define NBUF 7          // smem row slots (== vertical ring size)
#define LEAD 5          // cp.async lookahead depth
#define SROW 1032       // 4 pad + 1024 data + 4 pad floats per slot

__device__ float g_cube[(size_t)NVCH * NPIX * NPIX];   // 256 MB scratch
__device__ float g_g1d[8];

// ---------------------------------------------------------------- zero cube
__global__ __launch_bounds__(256) void zero_k() {
    float4* p = reinterpret_cast<float4*>(g_cube);
    const int n4 = NVCH * NPIX * NPIX / 4;
    float4 z = make_float4(0.f, 0.f, 0.f, 0.f);
    for (int i = blockIdx.x * 256 + threadIdx.x; i < n4; i += gridDim.x * 256)
        p[i] = z;
}

// ------------------------------------------------- recover separable 1D taps
__global__ void prep_k(const float* __restrict__ k2d) {
    int k = threadIdx.x;
    if (k < 7) {
        float s = 0.f;
        #pragma unroll
        for (int j = 0; j < 7; j++) s += k2d[k * 7 + j];
        g_g1d[k] = s;
    }
}

// ---------------------------------------------------------------- scatter
__global__ __launch_bounds__(256) void scatter_k(
    const float* __restrict__ pos,
    const float* __restrict__ vel,
    const float* __restrict__ flx,
    const float* __restrict__ vax,
    int M)
{
    int i = blockIdx.x * 256 + threadIdx.x;
    if (i >= M) return;

    float2 p = reinterpret_cast<const float2*>(pos)[i];
    float v  = vel[i];
    float f  = flx[i];

    float vel0 = __ldg(&vax[0]);
    float dv   = __fsub_rn(__ldg(&vax[1]), vel0);

    const float FOVH = 51.15f;
    int ix = (int)floorf(__fmul_rn(__fadd_rn(p.x, FOVH), 10.0f));
    int iy = (int)floorf(__fmul_rn(__fadd_rn(p.y, FOVH), 10.0f));
    int iv = (int)floorf(__fdiv_rn(__fsub_rn(v, vel0), dv));

    if ((unsigned)(ix + 4) >= (unsigned)(NPIX + 8)) return;
    if ((unsigned)(iy + 4) >= (unsigned)(NPIX + 8)) return;
    if ((unsigned)iv >= (unsigned)NVCH) return;

    int flat = (iv * NPIX + iy) * NPIX + ix;
    if ((unsigned)flat < (unsigned)(NVCH * NPIX * NPIX))
        atomicAdd(&g_cube[flat], f);
}

// ----- separable 7x7 conv, cp.async multistage row pipeline -----
// Block covers one full 1024-col row per step. Rows stream through a 7-slot
// circular smem buffer via fire-and-forget cp.async (depth LEAD=5), so load
// latency is hidden WITHOUT holding data in registers. Out-of-image rows and
// past-the-end tail issues use src_size=0 => hardware zero-fill (free halo).
// Left/right 4-float pads are zeroed once; cp.async never writes them.

__device__ __forceinline__ void cpa16(uint32_t saddr, const float* g, int sz) {
    asm volatile("cp.async.cg.shared.global [%0], [%1], 16, %2;"
                 :: "r"(saddr), "l"(g), "r"(sz));
}
__device__ __forceinline__ void cpa_commit() {
    asm volatile("cp.async.commit_group;");
}
__device__ __forceinline__ void cpa_wait() {
    asm volatile("cp.async.wait_group %0;" :: "n"(LEAD));
}

#define VERT(JJ, comp)                                                        \
    (g0*h[((JJ)+1)%7].comp + g1*h[((JJ)+2)%7].comp + g2*h[((JJ)+3)%7].comp +  \
     g3*h[((JJ)+4)%7].comp + g4*h[((JJ)+5)%7].comp + g5*h[((JJ)+6)%7].comp +  \
     g6*h[(JJ)%7].comp)

// issue row r of the band into slot SLOT (compile-time), zfill if invalid
#define ISSUE(SLOT, RR)                                                       \
{                                                                             \
    const int r = (RR);                                                       \
    const int y = y0 - 3 + r;                                                 \
    const bool vld = (r < RB + 6) && ((unsigned)y < (unsigned)NPIX);          \
    const float* g = cube + (size_t)(vld ? y : 0) * NPIX + (tid << 2);        \
    cpa16(sb + (SLOT) * (SROW * 4) + 16 + (tid << 4), g, vld ? 16 : 0);       \
    cpa_commit();                                                             \
}

#define CSTEP(J, IT)                                                          \
{                                                                             \
    const int it = (IT);                                                      \
    ISSUE(((J) + LEAD) % NBUF, it + LEAD)                                     \
    cpa_wait();                                                               \
    __syncthreads();                                                          \
    const float* rp = &srow[(J) % NBUF][tid << 2];                            \
    float4 hl = *(const float4*)(rp);          /* cols c-4..c-1 (padded) */   \
    float4 a  = *(const float4*)(rp + 4);      /* cols c..c+3  */             \
    float4 hr = *(const float4*)(rp + 8);      /* cols c+4..c+7 */            \
    float4 hx;                                                                \
    hx.x = hl.y*g0 + hl.z*g1 + hl.w*g2 + a.x*g3 + a.y*g4 + a.z*g5 + a.w*g6;   \
    hx.y = hl.z*g0 + hl.w*g1 + a.x*g2 + a.y*g3 + a.z*g4 + a.w*g5 + hr.x*g6;   \
    hx.z = hl.w*g0 + a.x*g1 + a.y*g2 + a.z*g3 + a.w*g4 + hr.x*g5 + hr.y*g6;   \
    hx.w = a.x*g0 + a.y*g1 + a.z*g2 + a.w*g3 + hr.x*g4 + hr.y*g5 + hr.z*g6;   \
    h[(J)%7] = hx;                                                            \
    if (it >= 6) {                                                            \
        float4 o;                                                             \
        o.x = VERT(J, x); o.y = VERT(J, y);                                   \
        o.z = VERT(J, z); o.w = VERT(J, w);                                   \
        *(float4*)(outc + (size_t)(y0 + it - 6) * NPIX + (tid << 2)) = o;     \
    }                                                                         \
}

__global__ __launch_bounds__(256) void conv_k(float* __restrict__ out) {
    __shared__ float srow[NBUF][SROW];

    const int tid = threadIdx.x;
    const int ch  = blockIdx.y;
    const int y0  = blockIdx.x * RB;

    const float* __restrict__ cube = g_cube + (size_t)ch * (NPIX * NPIX);
    float* __restrict__ outc = out + (size_t)ch * (NPIX * NPIX);

    const float g0 = g_g1d[0], g1 = g_g1d[1], g2 = g_g1d[2], g3 = g_g1d[3],
                g4 = g_g1d[4], g5 = g_g1d[5], g6 = g_g1d[6];

    const uint32_t sb = (uint32_t)__cvta_generic_to_shared(&srow[0][0]);

    // zero the 4-float left/right pads of every slot (visible at step-0 bar)
    if (tid < NBUF * 2) {
        float* p = &srow[tid >> 1][(tid & 1) ? (4 + NPIX) : 0];
        p[0] = p[1] = p[2] = p[3] = 0.f;
    }

    float4 h[7];

    // prologue: rows 0..4 into slots 0..4 (one commit group each)
    ISSUE(0, 0) ISSUE(1, 1) ISSUE(2, 2) ISSUE(3, 3) ISSUE(4, 4)

    // 134 steps: 19 chunks of 7 (it 0..132) + tail (it 133, slot 0)
    #pragma unroll 1
    for (int base = 0; base < RB + 5; base += 7) {
        CSTEP(0, base + 0)
        CSTEP(1, base + 1)
        CSTEP(2, base + 2)
        CSTEP(3, base + 3)
        CSTEP(4, base + 4)
        CSTEP(5, base + 5)
        CSTEP(6, base + 6)
    }
    CSTEP(0, RB + 5)    // it = 133, 133 % 7 == 0
}

extern "C" void kernel_launch(void* const* d_in, const int* in_sizes, int n_in,
                              void* d_out, int out_size) {
    const float* pos = (const float*)d_in[0];   // pos_img (M,2)
    const float* vel = (const float*)d_in[1];   // vel_chan (M,)
    const float* flx = (const float*)d_in[2];   // flux (M,)
    const float* vax = (const float*)d_in[3];   // vel_axis (64,)
    const float* k2d = (const float*)d_in[4];   // kernel2d (49,)
    float* out = (float*)d_out;

    int M = in_sizes[1];

    zero_k<<<4736, 256>>>();
    prep_k<<<1, 32>>>(k2d);
    scatter_k<<<(M + 255) / 256, 256>>>(pos, vel, flx, vax, M);

    dim3 grid(NPIX / RB, NVCH);
    conv_k<<<grid, 256>>>(out);
}